// round 16
// baseline (speedup 1.0000x reference)
#include <cuda_runtime.h>

// Problem constants (fixed shapes)
#define E_EDGES    320000
#define N_ATOMS_C  20000
#define TRIP_CAP_C 4000000
#define HALF_C     1280000        // speculative fill split (expected cnt ~1.17M)
#define D_MAX_C    64
#define NBLK       592            // 4 CTAs on each of 148 SMs: balanced wave
#define NTHR       512
#define CHUNK      542            // edges per block (even); 592*542 >= E
#define NPAIRB     271            // edge pairs per block (CHUNK/2)
#define CAP        3840           // staged triplets per block (expected ~1983)

// ---------------- scratch (device globals; no allocation allowed) ----------
// g_deg relies on zero-initialization at module load; every invocation
// re-zeros it at the end (nothing reads it after B3) for graph replay.
__device__ int g_deg[N_ATOMS_C];             // valid degree per node (self-reset)
__device__ int g_table[N_ATOMS_C * D_MAX_C]; // per-node edge slots (sorted P2b)
__device__ int g_bsum[NBLK];                 // per-block triplet-count partials
__device__ int g_bar_count;                  // barrier arrivals
__device__ int g_bar_gen;                    // barrier generation

// ---------------- grid-wide barrier (all NBLK blocks resident) --------------
__device__ __forceinline__ void grid_sync() {
    __syncthreads();
    if (threadIdx.x == 0) {
        int gen = *(volatile int*)&g_bar_gen;
        __threadfence();
        int t = atomicAdd(&g_bar_count, 1);
        if (t == NBLK - 1) {
            atomicExch(&g_bar_count, 0);
            __threadfence();
            atomicAdd(&g_bar_gen, 1);
        } else {
            while (*(volatile int*)&g_bar_gen == gen) { __nanosleep(32); }
        }
        __threadfence();
    }
    __syncthreads();
}

// ---------------- block-wide exclusive scan ---------------------------------
__device__ __forceinline__ int block_exscan(int v) {
    __shared__ int ws[32];
    int lane = threadIdx.x & 31, wid = threadIdx.x >> 5;
    int nw = NTHR >> 5;
    int x = v;
#pragma unroll
    for (int o = 1; o < 32; o <<= 1) {
        int y = __shfl_up_sync(0xffffffffu, x, o);
        if (lane >= o) x += y;
    }
    if (lane == 31) ws[wid] = x;
    __syncthreads();
    if (wid == 0) {
        int wv = (lane < nw) ? ws[lane] : 0;
        int wx = wv;
#pragma unroll
        for (int o = 1; o < 32; o <<= 1) {
            int y = __shfl_up_sync(0xffffffffu, wx, o);
            if (lane >= o) wx += y;
        }
        ws[lane] = wx - wv;
    }
    __syncthreads();
    int r = ws[wid] + x - v;
    __syncthreads();
    return r;
}

// classify one edge: returns row or -1, and does the table scatter.
// s <= 2.25f is exactly equivalent to sqrtf(s) <= 1.5f in fp32
// (2.25 exact; sqrt correctly-rounded & monotone) — saves a MUFU per edge.
__device__ __forceinline__ int classify_one(float x, float y, float z, int rr,
                                            int e) {
    float s = __fadd_rn(__fadd_rn(__fmul_rn(x, x), __fmul_rn(y, y)),
                        __fmul_rn(z, z));
    if (s <= 2.25f && rr >= 0 && rr < N_ATOMS_C) {
        int slot = atomicAdd(&g_deg[rr], 1);
        if (slot < D_MAX_C) g_table[rr * D_MAX_C + slot] = e;
        return rr;
    }
    return -1;
}

// ---------------- the whole pipeline in one persistent kernel ---------------
__global__ void __launch_bounds__(NTHR, 4)
k_triplets(const float* __restrict__ vec, const int* __restrict__ ei_row,
           float* __restrict__ out) {
    const int t = threadIdx.x, b = blockIdx.x;
    const int gid = b * NTHR + t;
    const int GT = NBLK * NTHR;

    __shared__ float2 s_pair[CAP];             // (ij, kj) staged per block
    __shared__ int s_bsum, s_boff, s_total;

    // Block-local edge pair mapping (same in P1/P2a/P4 -> balanced phases).
    // Rows r0/r1 live in REGISTERS across the barriers — no g_row array.
    const int base = b * CHUNK + 2 * t;
    const bool havep = (t < NPAIRB) && (base < E_EDGES);  // E even => base+1<E

    // P0: speculative fill of [HALF, TRIP_CAP) of both halves with -1.0f.
    // Correct for ANY count: if cnt > HALF, emit (post-B3, fence-ordered
    // after these stores via the grid barriers) overwrites the overlap.
    {
        float4 vm = make_float4(-1.0f, -1.0f, -1.0f, -1.0f);
        const int n4 = (TRIP_CAP_C - HALF_C) >> 2;
        float4* a = (float4*)(out + HALF_C);
        float4* c = (float4*)(out + TRIP_CAP_C + HALF_C);
        for (int i = gid; i < n4; i += GT) {
            a[i] = vm;
            c[i] = vm;
        }
    }

    // P1: classify + direct table scatter, 2 consecutive edges per thread.
    int r0 = -1, r1 = -1;
    if (havep) {
        const float2* v2 = (const float2*)(vec + 3 * base);
        float2 va = v2[0], vb = v2[1], vc = v2[2];
        int2 rr = *(const int2*)(ei_row + base);
        r0 = classify_one(va.x, va.y, vb.x, rr.x, base);
        r1 = classify_one(vb.y, vc.x, vc.y, rr.y, base + 1);
    }
    grid_sync();  // B2

    // P2a: per-block partial triplet counts; packed (row, d) kept in
    // registers for P4.
    int rv0 = -1, rv1 = -1;
    int lsum = 0;
    if (r0 >= 0) {
        int d = min(g_deg[r0], D_MAX_C);
        lsum += d - 1;
        rv0 = r0 | (d << 16);                  // r < 2^16, d <= 64
    }
    if (r1 >= 0) {
        int d = min(g_deg[r1], D_MAX_C);
        lsum += d - 1;
        rv1 = r1 | (d << 16);
    }
    int tpre = block_exscan(lsum);
    if (t == NTHR - 1) { g_bsum[b] = tpre + lsum; s_bsum = tpre + lsum; }

    // P2b: warp-parallel rank sort per node; shfl loop bounded by d.
    {
        const int lane = t & 31;
        const int wg = gid >> 5;
        const int NW = GT >> 5;
        for (int n = wg; n < N_ATOMS_C; n += NW) {
            int d = min(g_deg[n], D_MAX_C);
            if (d <= 1) continue;
            int* rowp = &g_table[n * D_MAX_C];
            if (d <= 32) {
                int v = (lane < d) ? rowp[lane] : 0x7fffffff;
                int rank = 0;
                for (int p = 0; p < d; p++) {
                    int vp = __shfl_sync(0xffffffffu, v, p);
                    rank += (vp < v) ? 1 : 0;
                }
                if (lane < d) rowp[rank] = v;
                __syncwarp();
            } else {
                if (lane == 0) {               // astronomically rare fallback
                    for (int i = 1; i < d; i++) {
                        int key = rowp[i];
                        int j = i - 1;
                        while (j >= 0 && rowp[j] > key) { rowp[j + 1] = rowp[j]; j--; }
                        rowp[j + 1] = key;
                    }
                }
                __syncwarp();
            }
        }
    }
    grid_sync();  // B3 — last read of g_deg is above

    // P3: every block redundantly scans the NBLK partials (two per thread,
    // NBLK = 592 > NTHR). Feeds emit immediately; g_deg reset deferred.
    {
        int i0 = 2 * t, i1 = 2 * t + 1;
        int v0 = (i0 < NBLK) ? g_bsum[i0] : 0;
        int v1 = (i1 < NBLK) ? g_bsum[i1] : 0;
        int ex = block_exscan(v0 + v1);
        if (i0 == b) s_boff = ex;
        if (i1 == b) s_boff = ex + v0;
        if (i1 == NBLK - 1) s_total = ex + v0 + v1;
    }
    __syncthreads();

    // P4: emit — stage block's contiguous run as float2 in SMEM (no bounds
    // checks: off < s_bsum <= CAP by scan construction), then
    // float2-vectorized coalesced copy-out. Checked fallback if run > CAP.
    {
        const bool fb = (s_bsum > CAP);
        int off = tpre;                        // block-local offset
        float* oj = out;
        float* ok = out + TRIP_CAP_C;
#pragma unroll
        for (int i = 0; i < 2; i++) {
            int e = base + i;
            int rv = (i == 0) ? rv0 : rv1;
            if (rv < 0) continue;
            int r = rv & 0xffff;
            int d = rv >> 16;
            const int4* rp4 = (const int4*)(g_table + r * D_MAX_C);
            float fe = (float)e;               // < 2^24, exact
            for (int q4 = 0; q4 < d; q4 += 4) {
                int4 v4 = rp4[q4 >> 2];
                int ks[4] = {v4.x, v4.y, v4.z, v4.w};
#pragma unroll
                for (int j = 0; j < 4; j++) {
                    int q = q4 + j;
                    if (q < d) {
                        int k = ks[j];
                        if (k != e) {
                            if (!fb) {
                                s_pair[off] = make_float2(fe, (float)k);
                            } else {
                                int p = s_boff + off;
                                if (p >= 0 && p < TRIP_CAP_C) {
                                    oj[p] = fe; ok[p] = (float)k;
                                }
                            }
                            off++;
                        }
                    }
                }
            }
        }
        __syncthreads();
        if (!fb) {
            int bs = s_bsum, gb = s_boff;
            int head = gb & 1;                 // make vector part 8B-aligned
            if (head && bs > 0 && t == 0) {
                float2 pr = s_pair[0];
                if (gb < TRIP_CAP_C) { oj[gb] = pr.x; ok[gb] = pr.y; }
            }
            int npair = (bs - head) >> 1;      // float2 pairs
            for (int j = t; j < npair; j += NTHR) {
                int i = head + 2 * j;
                int p = gb + i;
                if (p + 1 < TRIP_CAP_C) {
                    float2 a = s_pair[i], c = s_pair[i + 1];
                    *(float2*)(oj + p) = make_float2(a.x, c.x);
                    *(float2*)(ok + p) = make_float2(a.y, c.y);
                }
            }
            int rem = head + 2 * npair;        // 0 or 1 tail element
            if (rem < bs && t == 0) {
                int p = gb + rem;
                float2 pr = s_pair[rem];
                if (p < TRIP_CAP_C) { oj[p] = pr.x; ok[p] = pr.y; }
            }
        }
    }

    // P5: fill remaining dead region [cnt, HALF) of both halves.
    // Disjoint from emit's live prefix => no barrier needed.
    {
        int cnt = s_total;
        if (cnt < 0) cnt = 0;
        if (cnt < HALF_C) {
            int start4 = (cnt + 3) & ~3;
            if (start4 > HALF_C) start4 = HALF_C;
            float* oj = out;
            float* ok = out + TRIP_CAP_C;
            if (gid < start4 - cnt) {          // 0-3 head scalars per half
                oj[cnt + gid] = -1.0f;
                ok[cnt + gid] = -1.0f;
            }
            int n4 = (HALF_C - start4) >> 2;   // HALF_C % 4 == 0
            float4 vm = make_float4(-1.0f, -1.0f, -1.0f, -1.0f);
            float4* a = (float4*)(oj + start4);
            float4* c = (float4*)(ok + start4);
            for (int i = gid; i < n4; i += GT) {
                a[i] = vm;
                c[i] = vm;
            }
        }
    }

    // P6: reset g_deg for the next graph replay (off the critical path;
    // next invocation's first read is after its own B2).
    for (int i = gid; i < N_ATOMS_C; i += GT) g_deg[i] = 0;
}

// ---------------- launch -----------------------------------------------------
extern "C" void kernel_launch(void* const* d_in, const int* in_sizes, int n_in,
                              void* d_out, int out_size) {
    const float* vec    = (const float*)d_in[0];
    const int*   ei_row = (const int*)d_in[1];   // [2, E] int32; row = first E
    float* out = (float*)d_out;

    k_triplets<<<NBLK, NTHR>>>(vec, ei_row, out);
}

// round 17
// speedup vs baseline: 1.0362x; 1.0362x over previous
#include <cuda_runtime.h>

// Problem constants (fixed shapes)
#define E_EDGES    320000
#define N_ATOMS_C  20000
#define TRIP_CAP_C 4000000
#define HALF_C     1280000        // speculative fill split (expected cnt ~1.17M)
#define D_MAX_C    64
#define NBLK       592            // 4 CTAs on each of 148 SMs: balanced wave
#define NTHR       512
#define CHUNK      542            // edges per block (even); 592*542 >= E
#define NPAIRB     271            // edge pairs per block (CHUNK/2)
#define CAP        3840           // staged triplets per block (expected ~1983)

// ---------------- scratch (device globals; no allocation allowed) ----------
// g_deg relies on zero-initialization at module load; every invocation
// re-zeros it at the end (nothing reads it after B3) for graph replay.
__device__ int g_deg[N_ATOMS_C];             // valid degree per node (self-reset)
__device__ int g_table[N_ATOMS_C * D_MAX_C]; // per-node edge slots (sorted P2b)
__device__ int g_bsum[NBLK];                 // per-block triplet-count partials
__device__ int g_bar_count;                  // barrier arrivals
__device__ int g_bar_gen;                    // barrier generation

// ---------------- grid-wide barrier (all NBLK blocks resident) --------------
// Waiter: first probe free (late arrivals usually see the release already),
// then tight __ldcg poll on the L2-resident generation word — no nanosleep
// quantization on the release latency.
__device__ __forceinline__ void grid_sync() {
    __syncthreads();
    if (threadIdx.x == 0) {
        int gen = __ldcg(&g_bar_gen);
        __threadfence();                       // publish this block's writes
        int t = atomicAdd(&g_bar_count, 1);
        if (t == NBLK - 1) {
            atomicExch(&g_bar_count, 0);
            __threadfence();
            atomicAdd(&g_bar_gen, 1);          // release
        } else {
            if (__ldcg(&g_bar_gen) == gen) {   // fast path: maybe already done
                int spins = 0;
                while (__ldcg(&g_bar_gen) == gen) {
                    if (++spins > 64) { __nanosleep(32); }  // back off late
                }
            }
        }
        __threadfence();                       // acquire
    }
    __syncthreads();
}

// ---------------- block-wide exclusive scan ---------------------------------
__device__ __forceinline__ int block_exscan(int v) {
    __shared__ int ws[32];
    int lane = threadIdx.x & 31, wid = threadIdx.x >> 5;
    int nw = NTHR >> 5;
    int x = v;
#pragma unroll
    for (int o = 1; o < 32; o <<= 1) {
        int y = __shfl_up_sync(0xffffffffu, x, o);
        if (lane >= o) x += y;
    }
    if (lane == 31) ws[wid] = x;
    __syncthreads();
    if (wid == 0) {
        int wv = (lane < nw) ? ws[lane] : 0;
        int wx = wv;
#pragma unroll
        for (int o = 1; o < 32; o <<= 1) {
            int y = __shfl_up_sync(0xffffffffu, wx, o);
            if (lane >= o) wx += y;
        }
        ws[lane] = wx - wv;
    }
    __syncthreads();
    int r = ws[wid] + x - v;
    __syncthreads();
    return r;
}

// classify one edge: returns row or -1, and does the table scatter.
// s <= 2.25f is exactly equivalent to sqrtf(s) <= 1.5f in fp32
// (2.25 exact; sqrt correctly-rounded & monotone) — saves a MUFU per edge.
__device__ __forceinline__ int classify_one(float x, float y, float z, int rr,
                                            int e) {
    float s = __fadd_rn(__fadd_rn(__fmul_rn(x, x), __fmul_rn(y, y)),
                        __fmul_rn(z, z));
    if (s <= 2.25f && rr >= 0 && rr < N_ATOMS_C) {
        int slot = atomicAdd(&g_deg[rr], 1);
        if (slot < D_MAX_C) g_table[rr * D_MAX_C + slot] = e;
        return rr;
    }
    return -1;
}

// ---------------- the whole pipeline in one persistent kernel ---------------
__global__ void __launch_bounds__(NTHR, 4)
k_triplets(const float* __restrict__ vec, const int* __restrict__ ei_row,
           float* __restrict__ out) {
    const int t = threadIdx.x, b = blockIdx.x;
    const int gid = b * NTHR + t;
    const int GT = NBLK * NTHR;

    __shared__ float2 s_pair[CAP];             // (ij, kj) staged per block
    __shared__ int s_bsum, s_boff, s_total;

    // Block-local edge pair mapping (same in P1/P2a/P4 -> balanced phases).
    // Rows r0/r1 live in REGISTERS across the barriers — no g_row array.
    const int base = b * CHUNK + 2 * t;
    const bool havep = (t < NPAIRB) && (base < E_EDGES);  // E even => base+1<E

    // P0: speculative fill of [HALF, TRIP_CAP) of both halves with -1.0f.
    // Correct for ANY count: if cnt > HALF, emit (post-B3, fence-ordered
    // after these stores via the grid barriers) overwrites the overlap.
    {
        float4 vm = make_float4(-1.0f, -1.0f, -1.0f, -1.0f);
        const int n4 = (TRIP_CAP_C - HALF_C) >> 2;
        float4* a = (float4*)(out + HALF_C);
        float4* c = (float4*)(out + TRIP_CAP_C + HALF_C);
        for (int i = gid; i < n4; i += GT) {
            a[i] = vm;
            c[i] = vm;
        }
    }

    // P1: classify + direct table scatter, 2 consecutive edges per thread.
    int r0 = -1, r1 = -1;
    if (havep) {
        const float2* v2 = (const float2*)(vec + 3 * base);
        float2 va = v2[0], vb = v2[1], vc = v2[2];
        int2 rr = *(const int2*)(ei_row + base);
        r0 = classify_one(va.x, va.y, vb.x, rr.x, base);
        r1 = classify_one(vb.y, vc.x, vc.y, rr.y, base + 1);
    }
    grid_sync();  // B2

    // P2a: per-block partial triplet counts; packed (row, d) kept in
    // registers for P4.
    int rv0 = -1, rv1 = -1;
    int lsum = 0;
    if (r0 >= 0) {
        int d = min(g_deg[r0], D_MAX_C);
        lsum += d - 1;
        rv0 = r0 | (d << 16);                  // r < 2^16, d <= 64
    }
    if (r1 >= 0) {
        int d = min(g_deg[r1], D_MAX_C);
        lsum += d - 1;
        rv1 = r1 | (d << 16);
    }
    int tpre = block_exscan(lsum);
    if (t == NTHR - 1) { g_bsum[b] = tpre + lsum; s_bsum = tpre + lsum; }

    // P2b: warp-parallel rank sort per node; shfl loop bounded by d.
    {
        const int lane = t & 31;
        const int wg = gid >> 5;
        const int NW = GT >> 5;
        for (int n = wg; n < N_ATOMS_C; n += NW) {
            int d = min(g_deg[n], D_MAX_C);
            if (d <= 1) continue;
            int* rowp = &g_table[n * D_MAX_C];
            if (d <= 32) {
                int v = (lane < d) ? rowp[lane] : 0x7fffffff;
                int rank = 0;
                for (int p = 0; p < d; p++) {
                    int vp = __shfl_sync(0xffffffffu, v, p);
                    rank += (vp < v) ? 1 : 0;
                }
                if (lane < d) rowp[rank] = v;
                __syncwarp();
            } else {
                if (lane == 0) {               // astronomically rare fallback
                    for (int i = 1; i < d; i++) {
                        int key = rowp[i];
                        int j = i - 1;
                        while (j >= 0 && rowp[j] > key) { rowp[j + 1] = rowp[j]; j--; }
                        rowp[j + 1] = key;
                    }
                }
                __syncwarp();
            }
        }
    }
    grid_sync();  // B3 — last read of g_deg is above

    // P3: every block redundantly scans the NBLK partials (two per thread,
    // NBLK = 592 > NTHR). Feeds emit immediately; g_deg reset deferred.
    {
        int i0 = 2 * t, i1 = 2 * t + 1;
        int v0 = (i0 < NBLK) ? g_bsum[i0] : 0;
        int v1 = (i1 < NBLK) ? g_bsum[i1] : 0;
        int ex = block_exscan(v0 + v1);
        if (i0 == b) s_boff = ex;
        if (i1 == b) s_boff = ex + v0;
        if (i1 == NBLK - 1) s_total = ex + v0 + v1;
    }
    __syncthreads();

    // P4: emit — stage block's contiguous run as float2 in SMEM (no bounds
    // checks: off < s_bsum <= CAP by scan construction), then
    // float2-vectorized coalesced copy-out. Checked fallback if run > CAP.
    {
        const bool fb = (s_bsum > CAP);
        int off = tpre;                        // block-local offset
        float* oj = out;
        float* ok = out + TRIP_CAP_C;
#pragma unroll
        for (int i = 0; i < 2; i++) {
            int e = base + i;
            int rv = (i == 0) ? rv0 : rv1;
            if (rv < 0) continue;
            int r = rv & 0xffff;
            int d = rv >> 16;
            const int4* rp4 = (const int4*)(g_table + r * D_MAX_C);
            float fe = (float)e;               // < 2^24, exact
            for (int q4 = 0; q4 < d; q4 += 4) {
                int4 v4 = rp4[q4 >> 2];
                int ks[4] = {v4.x, v4.y, v4.z, v4.w};
#pragma unroll
                for (int j = 0; j < 4; j++) {
                    int q = q4 + j;
                    if (q < d) {
                        int k = ks[j];
                        if (k != e) {
                            if (!fb) {
                                s_pair[off] = make_float2(fe, (float)k);
                            } else {
                                int p = s_boff + off;
                                if (p >= 0 && p < TRIP_CAP_C) {
                                    oj[p] = fe; ok[p] = (float)k;
                                }
                            }
                            off++;
                        }
                    }
                }
            }
        }
        __syncthreads();
        if (!fb) {
            int bs = s_bsum, gb = s_boff;
            int head = gb & 1;                 // make vector part 8B-aligned
            if (head && bs > 0 && t == 0) {
                float2 pr = s_pair[0];
                if (gb < TRIP_CAP_C) { oj[gb] = pr.x; ok[gb] = pr.y; }
            }
            int npair = (bs - head) >> 1;      // float2 pairs
            for (int j = t; j < npair; j += NTHR) {
                int i = head + 2 * j;
                int p = gb + i;
                if (p + 1 < TRIP_CAP_C) {
                    float2 a = s_pair[i], c = s_pair[i + 1];
                    *(float2*)(oj + p) = make_float2(a.x, c.x);
                    *(float2*)(ok + p) = make_float2(a.y, c.y);
                }
            }
            int rem = head + 2 * npair;        // 0 or 1 tail element
            if (rem < bs && t == 0) {
                int p = gb + rem;
                float2 pr = s_pair[rem];
                if (p < TRIP_CAP_C) { oj[p] = pr.x; ok[p] = pr.y; }
            }
        }
    }

    // P5: fill remaining dead region [cnt, HALF) of both halves.
    // Disjoint from emit's live prefix => no barrier needed.
    {
        int cnt = s_total;
        if (cnt < 0) cnt = 0;
        if (cnt < HALF_C) {
            int start4 = (cnt + 3) & ~3;
            if (start4 > HALF_C) start4 = HALF_C;
            float* oj = out;
            float* ok = out + TRIP_CAP_C;
            if (gid < start4 - cnt) {          // 0-3 head scalars per half
                oj[cnt + gid] = -1.0f;
                ok[cnt + gid] = -1.0f;
            }
            int n4 = (HALF_C - start4) >> 2;   // HALF_C % 4 == 0
            float4 vm = make_float4(-1.0f, -1.0f, -1.0f, -1.0f);
            float4* a = (float4*)(oj + start4);
            float4* c = (float4*)(ok + start4);
            for (int i = gid; i < n4; i += GT) {
                a[i] = vm;
                c[i] = vm;
            }
        }
    }

    // P6: reset g_deg for the next graph replay (off the critical path;
    // next invocation's first read is after its own B2).
    for (int i = gid; i < N_ATOMS_C; i += GT) g_deg[i] = 0;
}

// ---------------- launch -----------------------------------------------------
extern "C" void kernel_launch(void* const* d_in, const int* in_sizes, int n_in,
                              void* d_out, int out_size) {
    const float* vec    = (const float*)d_in[0];
    const int*   ei_row = (const int*)d_in[1];   // [2, E] int32; row = first E
    float* out = (float*)d_out;

    k_triplets<<<NBLK, NTHR>>>(vec, ei_row, out);
}